// round 1
// baseline (speedup 1.0000x reference)
#include <cuda_runtime.h>
#include <math.h>

#define BATCH 8
#define NVERT 8192
#define NPD 64
#define NSAMP (NPD*NPD)      // 4096
#define CH 32                // K-chunks per batch
#define JCHUNK (NVERT/CH)    // 256
#define JT 32                // j's per stage
#define NSTAGE (JCHUNK/JT)   // 8

// Device scratch (no allocations allowed in kernel_launch)
__device__ float g_kx[BATCH];                       // CN*log2e / sigma^2
__device__ float g_coeff[BATCH];                    // CF / sigma^2 / NV
__device__ float g_partial[BATCH*CH*NSAMP];         // 4 MB partial GEMM results
__device__ float g_K[BATCH*NSAMP];                  // reduced, coeff-scaled

__device__ __forceinline__ float ex2f(float x) {
    float y;
    asm("ex2.approx.ftz.f32 %0, %1;" : "=f"(y) : "f"(x));
    return y;
}

// Packed 2xFP32 FMA (Blackwell FFMA2, PTX-only)
__device__ __forceinline__ unsigned long long ffma2(
    unsigned long long a, unsigned long long b, unsigned long long c)
{
    unsigned long long d;
    asm("fma.rn.f32x2 %0, %1, %2, %3;" : "=l"(d) : "l"(a), "l"(b), "l"(c));
    return d;
}

// -------------------- Kernel 1: sigma + constants --------------------
__global__ void k_sigma(const float* __restrict__ T) {
    int bb = blockIdx.x;
    int tid = threadIdx.x;                       // 256 threads
    const float4* t4 = (const float4*)(T + bb * NVERT * 2);   // 4096 float4/batch
    float sx = 0.f, sxx = 0.f, sy = 0.f, syy = 0.f;
    #pragma unroll
    for (int k = 0; k < 16; ++k) {
        float4 v = t4[tid + k * 256];            // (x0,y0,x1,y1)
        sx  += v.x + v.z;
        sy  += v.y + v.w;
        sxx += v.x * v.x + v.z * v.z;
        syy += v.y * v.y + v.w * v.w;
    }
    #pragma unroll
    for (int o = 16; o; o >>= 1) {
        sx  += __shfl_xor_sync(~0u, sx,  o);
        sxx += __shfl_xor_sync(~0u, sxx, o);
        sy  += __shfl_xor_sync(~0u, sy,  o);
        syy += __shfl_xor_sync(~0u, syy, o);
    }
    __shared__ float4 sred[8];
    if ((tid & 31) == 0) sred[tid >> 5] = make_float4(sx, sxx, sy, syy);
    __syncthreads();
    if (tid == 0) {
        double Sx = 0, Sxx = 0, Sy = 0, Syy = 0;
        #pragma unroll
        for (int w = 0; w < 8; ++w) {
            float4 r = sred[w];
            Sx += r.x; Sxx += r.y; Sy += r.z; Syy += r.w;
        }
        const double n = (double)NVERT;
        double vx = (Sxx - Sx * Sx / n) / (n - 1.0);
        double vy = (Syy - Sy * Sy / n) / (n - 1.0);
        if (vx < 0.0) vx = 0.0;
        if (vy < 0.0) vy = 0.0;
        double sigma = 0.5 * (sqrt(vx) + sqrt(vy));
        const double bd = 1.0 / 63.0;            // (U-L)/(NPD-1)
        if (sigma < bd) sigma = bd;
        // D=2: C = NV^{-1/6} = 2^{-13/6};  CN = -2^{13/3}/2;  CF = 2^{13/3}/(2*pi)
        const double p   = exp2(13.0 / 3.0);
        const double CNd = -0.5 * p;
        const double CFd = p / (2.0 * M_PI);
        const double s2  = sigma * sigma;
        g_kx[bb]    = (float)(CNd / s2 * 1.4426950408889634);   // * log2(e) for ex2
        g_coeff[bb] = (float)(CFd / s2 / (double)NVERT);
    }
}

// -------------------- Kernel 2: separable-KDE GEMM --------------------
// K[b][a*64+b'] = sum_j Ex[b,a,j] * Ey[b,b',j], chunked over j.
// Block = (batch, k-chunk). 128 threads; thread tile = 8(a) x 4(b').
__global__ void __launch_bounds__(128) k_main(const float* __restrict__ T,
                                              const float* __restrict__ S)
{
    __shared__ __align__(16) float2 sExd[JT][NPD];   // duplicated (ex,ex) pairs, 16 KB
    __shared__ __align__(16) float  sEy[JT][NPD];    // 8 KB
    __shared__ __align__(16) float2 sT[JCHUNK];      // 2 KB T chunk
    __shared__ float sG[NPD];                        // grid values

    const int tid = threadIdx.x;
    const int bb  = blockIdx.x >> 5;     // batch
    const int ch  = blockIdx.x & 31;     // k-chunk
    const int j0  = ch * JCHUNK;

    // Stage the T chunk (256 vertices) and grid into shared
    ((float4*)sT)[tid] = ((const float4*)(T + (bb * NVERT + j0) * 2))[tid];
    if (tid < NPD) sG[tid] = S[tid * 2 + 1];   // S[0, c, 1] = g[c] exactly
    const float kx = g_kx[bb];

    unsigned long long acc[8][2];
    #pragma unroll
    for (int i = 0; i < 8; ++i) { acc[i][0] = 0ull; acc[i][1] = 0ull; }

    const int ta = tid >> 4;          // 0..7  -> a rows [ta*8, ta*8+8)
    const int tb = tid & 15;          // 0..15 -> b' cols [tb*4, tb*4+4)
    const int av = tid & 63;          // fill-stage grid index
    const int jbase = tid >> 6;       // 0/1

    __syncthreads();
    const float ga = sG[av];

    for (int s = 0; s < NSTAGE; ++s) {
        // ---- fill stage: 32 j's x 64 grid points, x and y exps ----
        #pragma unroll
        for (int it = 0; it < 16; ++it) {
            int jj = it * 2 + jbase;
            float2 t = sT[s * JT + jj];
            float dx = ga - t.x;
            float dy = ga - t.y;
            float ex = ex2f(kx * (dx * dx));
            float ey = ex2f(kx * (dy * dy));
            sExd[jj][av] = make_float2(ex, ex);   // duplicated for f32x2 broadcast
            sEy[jj][av]  = ey;
        }
        __syncthreads();
        // ---- GEMM stage: rank-1 updates with packed FFMA2 ----
        #pragma unroll
        for (int jj = 0; jj < JT; ++jj) {
            const ulonglong2* axp = (const ulonglong2*)&sExd[jj][ta * 8];
            ulonglong2 bv = *(const ulonglong2*)&sEy[jj][tb * 4];
            #pragma unroll
            for (int i = 0; i < 4; ++i) {
                ulonglong2 ax = axp[i];            // (a_{2i} dup, a_{2i+1} dup)
                acc[2*i  ][0] = ffma2(ax.x, bv.x, acc[2*i  ][0]);
                acc[2*i  ][1] = ffma2(ax.x, bv.y, acc[2*i  ][1]);
                acc[2*i+1][0] = ffma2(ax.y, bv.x, acc[2*i+1][0]);
                acc[2*i+1][1] = ffma2(ax.y, bv.y, acc[2*i+1][1]);
            }
        }
        __syncthreads();
    }

    float* outp = g_partial + blockIdx.x * NSAMP;
    #pragma unroll
    for (int i = 0; i < 8; ++i) {
        ulonglong2 v; v.x = acc[i][0]; v.y = acc[i][1];
        *(ulonglong2*)(outp + (ta * 8 + i) * NPD + tb * 4) = v;
    }
}

// -------------------- Kernel 3: reduce partials + scale --------------------
__global__ void k_reduce() {
    int o4 = blockIdx.x * blockDim.x + threadIdx.x;  // 8192 threads, 4 floats each
    int bb = o4 >> 10;                               // 1024 float4 per batch image
    int i4 = o4 & 1023;
    const float4* p = (const float4*)g_partial + bb * CH * 1024 + i4;
    float4 s = make_float4(0.f, 0.f, 0.f, 0.f);
    #pragma unroll
    for (int c = 0; c < CH; ++c) {
        float4 v = p[c * 1024];
        s.x += v.x; s.y += v.y; s.z += v.z; s.w += v.w;
    }
    float cf = g_coeff[bb];
    s.x *= cf; s.y *= cf; s.z *= cf; s.w *= cf;
    ((float4*)g_K)[o4] = s;
}

// -------------------- Kernel 4: per-batch normalize --------------------
__global__ void k_norm(float* __restrict__ out) {
    int bb = blockIdx.x;
    int tid = threadIdx.x;                           // 256 threads
    const float4* kp = (const float4*)(g_K + bb * NSAMP);
    float4 v[4];
    float s = 0.f;
    #pragma unroll
    for (int k = 0; k < 4; ++k) {
        v[k] = kp[tid + k * 256];
        s += v[k].x + v[k].y + v[k].z + v[k].w;
    }
    #pragma unroll
    for (int o = 16; o; o >>= 1) s += __shfl_xor_sync(~0u, s, o);
    __shared__ float sw[8];
    __shared__ float stot;
    if ((tid & 31) == 0) sw[tid >> 5] = s;
    __syncthreads();
    if (tid == 0) {
        float t = 0.f;
        #pragma unroll
        for (int w = 0; w < 8; ++w) t += sw[w];
        stot = fmaxf(t, 1e-5f);
    }
    __syncthreads();
    float inv = 1.0f / stot;
    float4* op = (float4*)(out + bb * NSAMP);
    #pragma unroll
    for (int k = 0; k < 4; ++k) {
        float4 w = v[k];
        w.x *= inv; w.y *= inv; w.z *= inv; w.w *= inv;
        op[tid + k * 256] = w;
    }
}

extern "C" void kernel_launch(void* const* d_in, const int* in_sizes, int n_in,
                              void* d_out, int out_size)
{
    const float* T = (const float*)d_in[0];
    const float* S = (const float*)d_in[1];
    // Disambiguate by element counts: T has 8*8192*2, S has 8*4096*2
    if (n_in >= 2 && in_sizes[0] == BATCH * NSAMP * 2 &&
        in_sizes[1] == BATCH * NVERT * 2) {
        T = (const float*)d_in[1];
        S = (const float*)d_in[0];
    }
    k_sigma <<<BATCH, 256>>>(T);
    k_main  <<<BATCH * CH, 128>>>(T, S);
    k_reduce<<<32, 256>>>();
    k_norm  <<<BATCH, 256>>>((float*)d_out);
}

// round 2
// speedup vs baseline: 1.0082x; 1.0082x over previous
#include <cuda_runtime.h>
#include <math.h>

#define BATCH 8
#define NVERT 8192
#define NPD 64
#define NSAMP (NPD*NPD)      // 4096
#define CH 32                // K-chunks per batch
#define JCHUNK (NVERT/CH)    // 256
#define JT 16                // j's per stage (double-buffered)
#define NSTAGE (JCHUNK/JT)   // 16

// Device scratch (no allocations allowed)
__device__ float g_kx[BATCH];                       // CN*log2e / sigma^2
__device__ float g_coeff[BATCH];                    // CF / sigma^2 / NV
__device__ float g_partial[BATCH*CH*NSAMP];         // 4 MB partial GEMM results

__device__ __forceinline__ float ex2f(float x) {
    float y;
    asm("ex2.approx.ftz.f32 %0, %1;" : "=f"(y) : "f"(x));
    return y;
}

// Packed 2xFP32 FMA (Blackwell FFMA2, PTX-only)
__device__ __forceinline__ unsigned long long ffma2(
    unsigned long long a, unsigned long long b, unsigned long long c)
{
    unsigned long long d;
    asm("fma.rn.f32x2 %0, %1, %2, %3;" : "=l"(d) : "l"(a), "l"(b), "l"(c));
    return d;
}

// -------------------- Kernel 1: sigma + constants --------------------
__global__ void k_sigma(const float* __restrict__ T) {
    int bb = blockIdx.x;
    int tid = threadIdx.x;                       // 256 threads
    const float4* t4 = (const float4*)(T + bb * NVERT * 2);   // 4096 float4/batch
    float sx = 0.f, sxx = 0.f, sy = 0.f, syy = 0.f;
    #pragma unroll
    for (int k = 0; k < 16; ++k) {
        float4 v = t4[tid + k * 256];            // (x0,y0,x1,y1)
        sx  += v.x + v.z;
        sy  += v.y + v.w;
        sxx += v.x * v.x + v.z * v.z;
        syy += v.y * v.y + v.w * v.w;
    }
    #pragma unroll
    for (int o = 16; o; o >>= 1) {
        sx  += __shfl_xor_sync(~0u, sx,  o);
        sxx += __shfl_xor_sync(~0u, sxx, o);
        sy  += __shfl_xor_sync(~0u, sy,  o);
        syy += __shfl_xor_sync(~0u, syy, o);
    }
    __shared__ float4 sred[8];
    if ((tid & 31) == 0) sred[tid >> 5] = make_float4(sx, sxx, sy, syy);
    __syncthreads();
    if (tid == 0) {
        double Sx = 0, Sxx = 0, Sy = 0, Syy = 0;
        #pragma unroll
        for (int w = 0; w < 8; ++w) {
            float4 r = sred[w];
            Sx += r.x; Sxx += r.y; Sy += r.z; Syy += r.w;
        }
        const double n = (double)NVERT;
        double vx = (Sxx - Sx * Sx / n) / (n - 1.0);
        double vy = (Syy - Sy * Sy / n) / (n - 1.0);
        if (vx < 0.0) vx = 0.0;
        if (vy < 0.0) vy = 0.0;
        double sigma = 0.5 * (sqrt(vx) + sqrt(vy));
        const double bd = 1.0 / 63.0;            // (U-L)/(NPD-1)
        if (sigma < bd) sigma = bd;
        // D=2: C = NV^{-1/6} = 2^{-13/6};  CN = -2^{13/3}/2;  CF = 2^{13/3}/(2*pi)
        const double p   = exp2(13.0 / 3.0);
        const double CNd = -0.5 * p;
        const double CFd = p / (2.0 * M_PI);
        const double s2  = sigma * sigma;
        g_kx[bb]    = (float)(CNd / s2 * 1.4426950408889634);   // * log2(e) for ex2
        g_coeff[bb] = (float)(CFd / s2 / (double)NVERT);
    }
}

// -------------------- Kernel 2: separable-KDE GEMM (pipelined) --------------------
// K[b][a*64+b'] = sum_j Ex[b,a,j] * Ey[b,b',j], chunked over j.
// Double-buffered stages: MUFU fill of stage s+1 overlaps FFMA2 GEMM of stage s.
__global__ void __launch_bounds__(128) k_main(const float* __restrict__ T,
                                              const float* __restrict__ S)
{
    __shared__ __align__(16) float2 sExd[2][JT][NPD];   // duplicated (ex,ex), 2x8KB
    __shared__ __align__(16) float  sEy[2][JT][NPD];    // 2x4KB
    __shared__ __align__(16) float2 sT[JCHUNK];         // 2 KB T chunk
    __shared__ float sG[NPD];                           // grid values

    const int tid = threadIdx.x;
    const int bb  = blockIdx.x >> 5;     // batch
    const int ch  = blockIdx.x & 31;     // k-chunk
    const int j0  = ch * JCHUNK;

    // Stage the T chunk (256 vertices) and grid into shared
    ((float4*)sT)[tid] = ((const float4*)(T + (bb * NVERT + j0) * 2))[tid];
    if (tid < NPD) sG[tid] = S[tid * 2 + 1];   // S[0, c, 1] = g[c] exactly
    const float kx = g_kx[bb];

    unsigned long long acc[8][2];
    #pragma unroll
    for (int i = 0; i < 8; ++i) { acc[i][0] = 0ull; acc[i][1] = 0ull; }

    const int ta = tid >> 4;          // 0..7  -> a rows [ta*8, ta*8+8)
    const int tb = tid & 15;          // 0..15 -> b' cols [tb*4, tb*4+4)
    const int av = tid & 63;          // fill-stage grid index
    const int jbase = tid >> 6;       // 0/1

    __syncthreads();
    const float ga = sG[av];

    // Prologue: fill stage 0 into buffer 0
    #pragma unroll
    for (int it = 0; it < 8; ++it) {
        int jj = it * 2 + jbase;
        float2 t = sT[jj];
        float dx = ga - t.x;
        float dy = ga - t.y;
        float ex = ex2f(kx * (dx * dx));
        float ey = ex2f(kx * (dy * dy));
        sExd[0][jj][av] = make_float2(ex, ex);
        sEy[0][jj][av]  = ey;
    }
    __syncthreads();

    for (int s = 0; s < NSTAGE; ++s) {
        const int cur = s & 1;
        // ---- fill next stage (MUFU pipe) — overlaps with GEMM below ----
        if (s + 1 < NSTAGE) {
            const int nxt = cur ^ 1;
            #pragma unroll
            for (int it = 0; it < 8; ++it) {
                int jj = it * 2 + jbase;
                float2 t = sT[(s + 1) * JT + jj];
                float dx = ga - t.x;
                float dy = ga - t.y;
                float ex = ex2f(kx * (dx * dx));
                float ey = ex2f(kx * (dy * dy));
                sExd[nxt][jj][av] = make_float2(ex, ex);
                sEy[nxt][jj][av]  = ey;
            }
        }
        // ---- GEMM stage: rank-1 updates with packed FFMA2 (FMA pipe) ----
        #pragma unroll
        for (int jj = 0; jj < JT; ++jj) {
            const ulonglong2* axp = (const ulonglong2*)&sExd[cur][jj][ta * 8];
            ulonglong2 bv = *(const ulonglong2*)&sEy[cur][jj][tb * 4];
            #pragma unroll
            for (int i = 0; i < 4; ++i) {
                ulonglong2 ax = axp[i];            // (a_{2i} dup, a_{2i+1} dup)
                acc[2*i  ][0] = ffma2(ax.x, bv.x, acc[2*i  ][0]);
                acc[2*i  ][1] = ffma2(ax.x, bv.y, acc[2*i  ][1]);
                acc[2*i+1][0] = ffma2(ax.y, bv.x, acc[2*i+1][0]);
                acc[2*i+1][1] = ffma2(ax.y, bv.y, acc[2*i+1][1]);
            }
        }
        __syncthreads();
    }

    float* outp = g_partial + blockIdx.x * NSAMP;
    #pragma unroll
    for (int i = 0; i < 8; ++i) {
        ulonglong2 v; v.x = acc[i][0]; v.y = acc[i][1];
        *(ulonglong2*)(outp + (ta * 8 + i) * NPD + tb * 4) = v;
    }
}

// -------------------- Kernel 3: fused reduce + scale + normalize --------------------
// One block per batch, 1024 threads; each thread owns one float4 of the image.
__global__ void __launch_bounds__(1024) k_finish(float* __restrict__ out) {
    const int bb  = blockIdx.x;
    const int tid = threadIdx.x;                     // 0..1023, one float4 each
    const float4* p = (const float4*)g_partial + bb * CH * 1024 + tid;

    float4 s = make_float4(0.f, 0.f, 0.f, 0.f);
    #pragma unroll
    for (int c = 0; c < CH; ++c) {
        float4 v = p[c * 1024];
        s.x += v.x; s.y += v.y; s.z += v.z; s.w += v.w;
    }
    const float cf = g_coeff[bb];
    s.x *= cf; s.y *= cf; s.z *= cf; s.w *= cf;

    // block-wide deterministic sum
    float lsum = s.x + s.y + s.z + s.w;
    #pragma unroll
    for (int o = 16; o; o >>= 1) lsum += __shfl_xor_sync(~0u, lsum, o);
    __shared__ float sw[32];
    __shared__ float stot;
    if ((tid & 31) == 0) sw[tid >> 5] = lsum;
    __syncthreads();
    if (tid < 32) {
        float v = sw[tid];
        #pragma unroll
        for (int o = 16; o; o >>= 1) v += __shfl_xor_sync(~0u, v, o);
        if (tid == 0) stot = fmaxf(v, 1e-5f);
    }
    __syncthreads();
    const float inv = 1.0f / stot;
    s.x *= inv; s.y *= inv; s.z *= inv; s.w *= inv;
    ((float4*)(out + bb * NSAMP))[tid] = s;
}

extern "C" void kernel_launch(void* const* d_in, const int* in_sizes, int n_in,
                              void* d_out, int out_size)
{
    const float* T = (const float*)d_in[0];
    const float* S = (const float*)d_in[1];
    // Disambiguate by element counts: T has 8*8192*2, S has 8*4096*2
    if (n_in >= 2 && in_sizes[0] == BATCH * NSAMP * 2 &&
        in_sizes[1] == BATCH * NVERT * 2) {
        T = (const float*)d_in[1];
        S = (const float*)d_in[0];
    }
    k_sigma <<<BATCH, 256>>>(T);
    k_main  <<<BATCH * CH, 128>>>(T, S);
    k_finish<<<BATCH, 1024>>>((float*)d_out);
}